// round 8
// baseline (speedup 1.0000x reference)
#include <cuda_runtime.h>
#include <cuda_bf16.h>
#include <cstdint>

// Problem constants
#define NN     8192
#define IN_F   256
#define OUT_F  128
#define NE     262144
#define WORDS_PER_ROW (NN / 32)   // 256
#define CAP    2048               // per-row neighbor capacity; P(deg>CAP) ~ 0
#define ATH    512                // attn threads per block

// ---------------- scratch (static device globals; no runtime alloc) ----------------
__device__ float        g_P0 [NN * OUT_F];         // 4 MB split-K partial 0
__device__ float        g_P1 [NN * OUT_F];         // 4 MB split-K partial 1
__device__ float        g_Wh [NN * OUT_F];         // 4 MB
__device__ float        g_Wh1[NN];
__device__ float        g_Wh2[NN];
__device__ unsigned int g_adj[NN * WORDS_PER_ROW]; // 8 MB bitmask
__device__ int          g_mode;                    // 1 = int64 edge_index, 0 = int32

// ---------------- kernel: detect edge_index dtype ----------------
__global__ void detect_kernel(const long long* __restrict__ ei) {
    int t = threadIdx.x;                               // 32 threads
    long long v = ei[(size_t)t * (2 * NE / 32 / 2)];   // spread over first half
    int bad = (v < 0 || v >= NN) ? 1 : 0;
    unsigned m = __ballot_sync(0xffffffffu, bad);
    if (t == 0) g_mode = (m == 0u) ? 1 : 0;
}

// ---------------- kernel: clear adjacency bitmask (vectorized) ----------------
__global__ void clear_adj_kernel() {
    size_t idx = (size_t)blockIdx.x * blockDim.x + threadIdx.x;
    size_t n4  = (size_t)NN * WORDS_PER_ROW / 4;
    if (idx < n4) reinterpret_cast<uint4*>(g_adj)[idx] = make_uint4(0u, 0u, 0u, 0u);
}

// ---------------- kernel: scatter edges into bitmask (dedup via OR) ----------------
__global__ void scatter_kernel(const void* __restrict__ eptr) {
    int e = blockIdx.x * blockDim.x + threadIdx.x;
    if (e >= NE) return;
    int i, j;
    if (g_mode) {
        const long long* p = (const long long*)eptr;
        i = (int)p[e];
        j = (int)p[NE + e];
    } else {
        const int* p = (const int*)eptr;
        i = p[e];
        j = p[NE + e];
    }
    i &= (NN - 1);
    j &= (NN - 1);
    atomicOr(&g_adj[i * WORDS_PER_ROW + (j >> 5)], 1u << (j & 31));
}

// ---------------- kernel: split-K GEMM, kk-unrolled x4 with float4 smem reads ------
// grid = 512: blockIdx>>1 = row tile (32 rows), blockIdx&1 = K half (128).
// 256 threads; thread (ty,tx) computes rows ty*4..+3, cols tx*4..+3.
__global__ void gemm_kernel(const float* __restrict__ h, const float* __restrict__ W) {
    __shared__ float hs[32][32];
    __shared__ float Ws[32][128];
    const int row0 = (blockIdx.x >> 1) * 32;
    const int ks   = (blockIdx.x & 1) * 128;
    const int tid  = threadIdx.x;
    const int tx   = tid & 31;
    const int ty   = tid >> 5;

    float acc[4][4];
    #pragma unroll
    for (int r = 0; r < 4; r++)
        #pragma unroll
        for (int c = 0; c < 4; c++) acc[r][c] = 0.f;

    #pragma unroll
    for (int kt = 0; kt < 128; kt += 32) {
        const int k0 = ks + kt;
        {   // hs: 32x32; one float4 per thread, coalesced
            int r  = tid >> 3;
            int kq = (tid & 7) * 4;
            *reinterpret_cast<float4*>(&hs[r][kq]) =
                *reinterpret_cast<const float4*>(&h[(size_t)(row0 + r) * IN_F + k0 + kq]);
        }
        #pragma unroll
        for (int q = 0; q < 4; q++) {   // Ws: 32x128; four float4 per thread
            int kk = ty + q * 8;
            *reinterpret_cast<float4*>(&Ws[kk][tx * 4]) =
                *reinterpret_cast<const float4*>(&W[(size_t)(k0 + kk) * OUT_F + tx * 4]);
        }
        __syncthreads();
        #pragma unroll
        for (int kk = 0; kk < 32; kk += 4) {
            float4 b0 = *reinterpret_cast<const float4*>(&Ws[kk + 0][tx * 4]);
            float4 b1 = *reinterpret_cast<const float4*>(&Ws[kk + 1][tx * 4]);
            float4 b2 = *reinterpret_cast<const float4*>(&Ws[kk + 2][tx * 4]);
            float4 b3 = *reinterpret_cast<const float4*>(&Ws[kk + 3][tx * 4]);
            #pragma unroll
            for (int r = 0; r < 4; r++) {
                float4 av = *reinterpret_cast<const float4*>(&hs[ty * 4 + r][kk]); // broadcast
                acc[r][0] = fmaf(av.x, b0.x, acc[r][0]);
                acc[r][1] = fmaf(av.x, b0.y, acc[r][1]);
                acc[r][2] = fmaf(av.x, b0.z, acc[r][2]);
                acc[r][3] = fmaf(av.x, b0.w, acc[r][3]);
                acc[r][0] = fmaf(av.y, b1.x, acc[r][0]);
                acc[r][1] = fmaf(av.y, b1.y, acc[r][1]);
                acc[r][2] = fmaf(av.y, b1.z, acc[r][2]);
                acc[r][3] = fmaf(av.y, b1.w, acc[r][3]);
                acc[r][0] = fmaf(av.z, b2.x, acc[r][0]);
                acc[r][1] = fmaf(av.z, b2.y, acc[r][1]);
                acc[r][2] = fmaf(av.z, b2.z, acc[r][2]);
                acc[r][3] = fmaf(av.z, b2.w, acc[r][3]);
                acc[r][0] = fmaf(av.w, b3.x, acc[r][0]);
                acc[r][1] = fmaf(av.w, b3.y, acc[r][1]);
                acc[r][2] = fmaf(av.w, b3.z, acc[r][2]);
                acc[r][3] = fmaf(av.w, b3.w, acc[r][3]);
            }
        }
        __syncthreads();
    }
    float* dst = (blockIdx.x & 1) ? g_P1 : g_P0;
    #pragma unroll
    for (int r = 0; r < 4; r++)
        *reinterpret_cast<float4*>(&dst[(size_t)(row0 + ty * 4 + r) * OUT_F + tx * 4]) =
            make_float4(acc[r][0], acc[r][1], acc[r][2], acc[r][3]);
}

// ---------------- kernel: epilogue — Wh = P0+P1, Wh1/Wh2 dots fused ----------------
__global__ void epi_kernel(const float* __restrict__ a) {
    const int row0 = blockIdx.x * 32;
    const int tid  = threadIdx.x;
    const int tx   = tid & 31;
    const int ty   = tid >> 5;

    const float4 a1 = *reinterpret_cast<const float4*>(&a[tx * 4]);
    const float4 a2 = *reinterpret_cast<const float4*>(&a[OUT_F + tx * 4]);

    float p1[4], p2[4];
    #pragma unroll
    for (int r = 0; r < 4; r++) {
        size_t off = (size_t)(row0 + ty * 4 + r) * OUT_F + tx * 4;
        float4 v0 = *reinterpret_cast<const float4*>(&g_P0[off]);
        float4 v1 = *reinterpret_cast<const float4*>(&g_P1[off]);
        float4 w  = make_float4(v0.x + v1.x, v0.y + v1.y, v0.z + v1.z, v0.w + v1.w);
        *reinterpret_cast<float4*>(&g_Wh[off]) = w;
        p1[r] = fmaf(w.x, a1.x, fmaf(w.y, a1.y, fmaf(w.z, a1.z, w.w * a1.w)));
        p2[r] = fmaf(w.x, a2.x, fmaf(w.y, a2.y, fmaf(w.z, a2.z, w.w * a2.w)));
    }
    #pragma unroll
    for (int o = 16; o > 0; o >>= 1) {
        #pragma unroll
        for (int r = 0; r < 4; r++) {
            p1[r] += __shfl_xor_sync(0xffffffffu, p1[r], o);
            p2[r] += __shfl_xor_sync(0xffffffffu, p2[r], o);
        }
    }
    if (tx == 0) {
        #pragma unroll
        for (int r = 0; r < 4; r++) {
            g_Wh1[row0 + ty * 4 + r] = p1[r];
            g_Wh2[row0 + ty * 4 + r] = p2[r];
        }
    }
}

// ---------------- block-wide exclusive scan over 512 threads (16 warps) ------------
__device__ __forceinline__ int block_scan_excl512(int val, int tid,
                                                  int* s_warp, int* s_total) {
    int lane = tid & 31, wid = tid >> 5;
    int incl = val;
    #pragma unroll
    for (int o = 1; o < 32; o <<= 1) {
        int n = __shfl_up_sync(0xffffffffu, incl, o);
        if (lane >= o) incl += n;
    }
    if (lane == 31) s_warp[wid] = incl;
    __syncthreads();
    if (wid == 0 && lane < 16) {
        int v = s_warp[lane];
        int inc2 = v;
        #pragma unroll
        for (int o = 1; o < 16; o <<= 1) {
            int n = __shfl_up_sync(0xffffu, inc2, o);
            if (lane >= o) inc2 += n;
        }
        s_warp[lane] = inc2 - v;
        if (lane == 15) *s_total = inc2;
    }
    __syncthreads();
    return (incl - val) + s_warp[wid];
}

// ---------------- kernel: fused sparse attention + aggregation + elu ----------------
// one block (512 thr) per row i
__global__ void attn_kernel(const float* __restrict__ S,
                            const float* __restrict__ raw_gamma,
                            float* __restrict__ out) {
    const int i   = blockIdx.x;
    if (i >= NN) return;
    const int tid = threadIdx.x;
    const int lane = tid & 31, wid = tid >> 5;

    __shared__ int   s_j[CAP];
    __shared__ float s_v[CAP];
    __shared__ int   s_warp[16];
    __shared__ int   s_total;
    __shared__ float s_red[16];
    __shared__ float s_bcast;
    __shared__ float s_fm[ATH];
    __shared__ int   s_fi[ATH];

    const float gamma = log1pf(expf(raw_gamma[0]));  // softplus
    const float wh1   = g_Wh1[i];

    // --- gather neighbor list from bitmask, deterministic order (sorted by j) ---
    unsigned w = (tid < WORDS_PER_ROW) ? g_adj[i * WORDS_PER_ROW + tid] : 0u;
    int nloc = __popc(w);
    int pos  = block_scan_excl512(nloc, tid, s_warp, &s_total);
    int total = s_total;

    while (w) {
        int b = __ffs(w) - 1;
        w &= w - 1;
        int j = (tid << 5) + b;
        float x = wh1 + g_Wh2[j];
        float e = (x > 0.f) ? x : 0.2f * x;                         // leaky_relu
        float v = e * fmaf(gamma, S[(size_t)i * NN + j], 1.0f);     // *(1+gamma*S)
        if (pos < CAP) { s_j[pos] = j; s_v[pos] = v; }
        pos++;
    }
    __syncthreads();
    int cnt = min(total, CAP);

    if (cnt == 0) {
        // all-masked row: softmax one-hot at argmax(-9e15*(1+g*S)) = argmin S
        float bm = 3.4e38f; int bj = 0;
        for (int j = tid; j < NN; j += ATH) {
            float s = S[(size_t)i * NN + j];
            if (s < bm) { bm = s; bj = j; }
        }
        s_fm[tid] = bm; s_fi[tid] = bj;
        __syncthreads();
        for (int s = ATH / 2; s > 0; s >>= 1) {
            if (tid < s) {
                if (s_fm[tid + s] < s_fm[tid] ||
                    (s_fm[tid + s] == s_fm[tid] && s_fi[tid + s] < s_fi[tid])) {
                    s_fm[tid] = s_fm[tid + s]; s_fi[tid] = s_fi[tid + s];
                }
            }
            __syncthreads();
        }
        if (tid < OUT_F) {
            float r = g_Wh[(size_t)s_fi[0] * OUT_F + tid];
            out[(size_t)i * OUT_F + tid] = (r > 0.f) ? r : expm1f(r);
        }
        return;
    }

    // --- row max (stable softmax) ---
    float m = -3.4e38f;
    for (int k = tid; k < cnt; k += ATH) m = fmaxf(m, s_v[k]);
    #pragma unroll
    for (int o = 16; o > 0; o >>= 1) m = fmaxf(m, __shfl_xor_sync(0xffffffffu, m, o));
    if (lane == 0) s_red[wid] = m;
    __syncthreads();
    if (tid == 0) {
        float mm = s_red[0];
        #pragma unroll
        for (int q = 1; q < 16; q++) mm = fmaxf(mm, s_red[q]);
        s_bcast = mm;
    }
    __syncthreads();
    m = s_bcast;
    __syncthreads();           // s_bcast is rewritten below

    // --- exponentiate in place + row sum ---
    float ls = 0.f;
    for (int k = tid; k < cnt; k += ATH) {
        float p = __expf(s_v[k] - m);
        s_v[k] = p;
        ls += p;
    }
    #pragma unroll
    for (int o = 16; o > 0; o >>= 1) ls += __shfl_xor_sync(0xffffffffu, ls, o);
    if (lane == 0) s_red[wid] = ls;
    __syncthreads();
    if (tid == 0) {
        float tt = 0.f;
        #pragma unroll
        for (int q = 0; q < 16; q++) tt += s_red[q];
        s_bcast = tt;
    }
    __syncthreads();
    const float inv_l = 1.0f / s_bcast;

    // --- weighted aggregation of Wh rows (4-way parallel over k) + elu ---
    {
        const int col  = tid & 127;
        const int part = tid >> 7;        // 0..3
        float acc = 0.f;
        for (int k = part; k < cnt; k += 4)
            acc = fmaf(s_v[k], g_Wh[(size_t)s_j[k] * OUT_F + col], acc);
        s_fm[tid] = acc;
        __syncthreads();
        if (tid < OUT_F) {
            float r = (s_fm[tid] + s_fm[tid + 128]) +
                      (s_fm[tid + 256] + s_fm[tid + 384]);
            r *= inv_l;
            out[(size_t)i * OUT_F + tid] = (r > 0.f) ? r : expm1f(r);
        }
    }
}

// ---------------- launch ----------------
extern "C" void kernel_launch(void* const* d_in, const int* in_sizes, int n_in,
                              void* d_out, int out_size) {
    const float* p_h = nullptr;
    const void*  p_e = nullptr;
    const float* p_S = nullptr;
    const float* p_W = nullptr;
    const float* p_a = nullptr;
    const float* p_g = nullptr;

    for (int k = 0; k < n_in; k++) {
        switch (in_sizes[k]) {
            case NN * IN_F:    p_h = (const float*)d_in[k]; break; // 2097152
            case 2 * NE:       p_e = d_in[k];               break; // 524288
            case NN * NN:      p_S = (const float*)d_in[k]; break; // 67108864
            case IN_F * OUT_F: p_W = (const float*)d_in[k]; break; // 32768
            case 2 * OUT_F:    p_a = (const float*)d_in[k]; break; // 256
            case 1:            p_g = (const float*)d_in[k]; break;
        }
    }
    float* out = (float*)d_out;

    detect_kernel<<<1, 32>>>((const long long*)p_e);
    clear_adj_kernel<<<(NN * WORDS_PER_ROW / 4 + 255) / 256, 256>>>();
    scatter_kernel<<<(NE + 255) / 256, 256>>>(p_e);
    gemm_kernel<<<512, 256>>>(p_h, p_W);
    epi_kernel<<<NN / 32, 256>>>(p_a);
    attn_kernel<<<NN, ATH>>>(p_S, p_g, out);
}

// round 9
// speedup vs baseline: 1.5382x; 1.5382x over previous
#include <cuda_runtime.h>
#include <cuda_bf16.h>
#include <cstdint>

// Problem constants
#define NN     8192
#define IN_F   256
#define OUT_F  128
#define NE     262144
#define WORDS_PER_ROW (NN / 32)   // 256
#define CAP    2048               // per-row neighbor capacity; P(deg>CAP) ~ 0

// ---------------- scratch (static device globals; no runtime alloc) ----------------
__device__ float        g_P0 [NN * OUT_F];         // 4 MB split-K partial 0
__device__ float        g_P1 [NN * OUT_F];         // 4 MB split-K partial 1
__device__ float        g_Wh [NN * OUT_F];         // 4 MB
__device__ float        g_Wh1[NN];
__device__ float        g_Wh2[NN];
__device__ unsigned int g_adj[NN * WORDS_PER_ROW]; // 8 MB bitmask
__device__ int          g_mode;                    // 1 = int64 edge_index, 0 = int32

// ---------------- kernel: detect edge_index dtype ----------------
__global__ void detect_kernel(const long long* __restrict__ ei) {
    int t = threadIdx.x;                               // 32 threads
    long long v = ei[(size_t)t * (2 * NE / 32 / 2)];   // spread over first half
    int bad = (v < 0 || v >= NN) ? 1 : 0;
    unsigned m = __ballot_sync(0xffffffffu, bad);
    if (t == 0) g_mode = (m == 0u) ? 1 : 0;
}

// ---------------- kernel: clear adjacency bitmask (vectorized) ----------------
__global__ void clear_adj_kernel() {
    size_t idx = (size_t)blockIdx.x * blockDim.x + threadIdx.x;
    size_t n4  = (size_t)NN * WORDS_PER_ROW / 4;
    if (idx < n4) reinterpret_cast<uint4*>(g_adj)[idx] = make_uint4(0u, 0u, 0u, 0u);
}

// ---------------- kernel: scatter edges into bitmask (dedup via OR) ----------------
__global__ void scatter_kernel(const void* __restrict__ eptr) {
    int e = blockIdx.x * blockDim.x + threadIdx.x;
    if (e >= NE) return;
    int i, j;
    if (g_mode) {
        const long long* p = (const long long*)eptr;
        i = (int)p[e];
        j = (int)p[NE + e];
    } else {
        const int* p = (const int*)eptr;
        i = p[e];
        j = p[NE + e];
    }
    i &= (NN - 1);
    j &= (NN - 1);
    atomicOr(&g_adj[i * WORDS_PER_ROW + (j >> 5)], 1u << (j & 31));
}

// ---------------- kernel: split-K GEMM, 8 rows x 4 cols per thread ----------------
// grid = 512: blockIdx>>1 = row tile (32 rows), blockIdx&1 = K half (128).
// 128 threads: tx = tid&31 -> cols tx*4..+3 ; ty = tid>>5 (0..3) -> rows ty*8..+7.
__global__ void gemm_kernel(const float* __restrict__ h, const float* __restrict__ W) {
    __shared__ float hs[32][32];
    __shared__ float Ws[32][128];
    const int row0 = (blockIdx.x >> 1) * 32;
    const int ks   = (blockIdx.x & 1) * 128;
    const int tid  = threadIdx.x;
    const int tx   = tid & 31;
    const int ty   = tid >> 5;

    float acc[8][4];
    #pragma unroll
    for (int r = 0; r < 8; r++)
        #pragma unroll
        for (int c = 0; c < 4; c++) acc[r][c] = 0.f;

    #pragma unroll
    for (int kt = 0; kt < 128; kt += 32) {
        const int k0 = ks + kt;
        // hs: 32x32 floats = 256 float4; 2 per thread (coalesced)
        #pragma unroll
        for (int q = 0; q < 2; q++) {
            int idx = tid + q * 128;       // 0..255
            int r   = idx >> 3;            // 0..31
            int c4  = (idx & 7) * 4;       // 0,4,...,28
            *reinterpret_cast<float4*>(&hs[r][c4]) =
                *reinterpret_cast<const float4*>(&h[(size_t)(row0 + r) * IN_F + k0 + c4]);
        }
        // Ws: 32x128 floats = 1024 float4; 8 per thread (coalesced: warp covers a row)
        #pragma unroll
        for (int q = 0; q < 8; q++) {
            int kk = ty + q * 4;           // 0..31
            *reinterpret_cast<float4*>(&Ws[kk][tx * 4]) =
                *reinterpret_cast<const float4*>(&W[(size_t)(k0 + kk) * OUT_F + tx * 4]);
        }
        __syncthreads();
        #pragma unroll
        for (int kk = 0; kk < 32; kk += 4) {
            float4 b0 = *reinterpret_cast<const float4*>(&Ws[kk + 0][tx * 4]);
            float4 b1 = *reinterpret_cast<const float4*>(&Ws[kk + 1][tx * 4]);
            float4 b2 = *reinterpret_cast<const float4*>(&Ws[kk + 2][tx * 4]);
            float4 b3 = *reinterpret_cast<const float4*>(&Ws[kk + 3][tx * 4]);
            #pragma unroll
            for (int r = 0; r < 8; r++) {
                float4 av = *reinterpret_cast<const float4*>(&hs[ty * 8 + r][kk]); // broadcast
                acc[r][0] = fmaf(av.x, b0.x, acc[r][0]);
                acc[r][1] = fmaf(av.x, b0.y, acc[r][1]);
                acc[r][2] = fmaf(av.x, b0.z, acc[r][2]);
                acc[r][3] = fmaf(av.x, b0.w, acc[r][3]);
                acc[r][0] = fmaf(av.y, b1.x, acc[r][0]);
                acc[r][1] = fmaf(av.y, b1.y, acc[r][1]);
                acc[r][2] = fmaf(av.y, b1.z, acc[r][2]);
                acc[r][3] = fmaf(av.y, b1.w, acc[r][3]);
                acc[r][0] = fmaf(av.z, b2.x, acc[r][0]);
                acc[r][1] = fmaf(av.z, b2.y, acc[r][1]);
                acc[r][2] = fmaf(av.z, b2.z, acc[r][2]);
                acc[r][3] = fmaf(av.z, b2.w, acc[r][3]);
                acc[r][0] = fmaf(av.w, b3.x, acc[r][0]);
                acc[r][1] = fmaf(av.w, b3.y, acc[r][1]);
                acc[r][2] = fmaf(av.w, b3.z, acc[r][2]);
                acc[r][3] = fmaf(av.w, b3.w, acc[r][3]);
            }
        }
        __syncthreads();
    }
    float* dst = (blockIdx.x & 1) ? g_P1 : g_P0;
    #pragma unroll
    for (int r = 0; r < 8; r++)
        *reinterpret_cast<float4*>(&dst[(size_t)(row0 + ty * 8 + r) * OUT_F + tx * 4]) =
            make_float4(acc[r][0], acc[r][1], acc[r][2], acc[r][3]);
}

// ---------------- kernel: epilogue — Wh = P0+P1, Wh1/Wh2 dots fused ----------------
__global__ void epi_kernel(const float* __restrict__ a) {
    const int row0 = blockIdx.x * 32;
    const int tid  = threadIdx.x;
    const int tx   = tid & 31;
    const int ty   = tid >> 5;

    const float4 a1 = *reinterpret_cast<const float4*>(&a[tx * 4]);
    const float4 a2 = *reinterpret_cast<const float4*>(&a[OUT_F + tx * 4]);

    float p1[4], p2[4];
    #pragma unroll
    for (int r = 0; r < 4; r++) {
        size_t off = (size_t)(row0 + ty * 4 + r) * OUT_F + tx * 4;
        float4 v0 = *reinterpret_cast<const float4*>(&g_P0[off]);
        float4 v1 = *reinterpret_cast<const float4*>(&g_P1[off]);
        float4 w  = make_float4(v0.x + v1.x, v0.y + v1.y, v0.z + v1.z, v0.w + v1.w);
        *reinterpret_cast<float4*>(&g_Wh[off]) = w;
        p1[r] = fmaf(w.x, a1.x, fmaf(w.y, a1.y, fmaf(w.z, a1.z, w.w * a1.w)));
        p2[r] = fmaf(w.x, a2.x, fmaf(w.y, a2.y, fmaf(w.z, a2.z, w.w * a2.w)));
    }
    #pragma unroll
    for (int o = 16; o > 0; o >>= 1) {
        #pragma unroll
        for (int r = 0; r < 4; r++) {
            p1[r] += __shfl_xor_sync(0xffffffffu, p1[r], o);
            p2[r] += __shfl_xor_sync(0xffffffffu, p2[r], o);
        }
    }
    if (tx == 0) {
        #pragma unroll
        for (int r = 0; r < 4; r++) {
            g_Wh1[row0 + ty * 4 + r] = p1[r];
            g_Wh2[row0 + ty * 4 + r] = p2[r];
        }
    }
}

// ---------------- block-wide exclusive scan over 256 threads (deterministic) --------
__device__ __forceinline__ int block_scan_excl256(int val, int tid,
                                                  int* s_warp, int* s_total) {
    int lane = tid & 31, wid = tid >> 5;
    int incl = val;
    #pragma unroll
    for (int o = 1; o < 32; o <<= 1) {
        int n = __shfl_up_sync(0xffffffffu, incl, o);
        if (lane >= o) incl += n;
    }
    if (lane == 31) s_warp[wid] = incl;
    __syncthreads();
    if (wid == 0 && lane < 8) {
        int v = s_warp[lane];
        int inc2 = v;
        #pragma unroll
        for (int o = 1; o < 8; o <<= 1) {
            int n = __shfl_up_sync(0xffu, inc2, o);
            if (lane >= o) inc2 += n;
        }
        s_warp[lane] = inc2 - v;          // exclusive warp offsets
        if (lane == 7) *s_total = inc2;   // grand total
    }
    __syncthreads();
    return (incl - val) + s_warp[wid];
}

// ---------------- kernel: fused sparse attention + aggregation + elu ----------------
// one block (256 thr) per row i  [R7 proven version]
__global__ void attn_kernel(const float* __restrict__ S,
                            const float* __restrict__ raw_gamma,
                            float* __restrict__ out) {
    const int i   = blockIdx.x;
    if (i >= NN) return;
    const int tid = threadIdx.x;
    const int lane = tid & 31, wid = tid >> 5;

    __shared__ int   s_j[CAP];
    __shared__ float s_v[CAP];
    __shared__ int   s_warp[8];
    __shared__ int   s_total;
    __shared__ float s_red[8];
    __shared__ float s_bcast;
    __shared__ float s_fm[256];
    __shared__ int   s_fi[256];

    const float gamma = log1pf(expf(raw_gamma[0]));  // softplus
    const float wh1   = g_Wh1[i];

    // --- gather neighbor list from bitmask, deterministic order (sorted by j) ---
    unsigned w = g_adj[i * WORDS_PER_ROW + tid];
    int nloc = __popc(w);
    int pos  = block_scan_excl256(nloc, tid, s_warp, &s_total);
    int total = s_total;

    while (w) {
        int b = __ffs(w) - 1;
        w &= w - 1;
        int j = (tid << 5) + b;
        float x = wh1 + g_Wh2[j];
        float e = (x > 0.f) ? x : 0.2f * x;                         // leaky_relu
        float v = e * fmaf(gamma, S[(size_t)i * NN + j], 1.0f);     // *(1+gamma*S)
        if (pos < CAP) { s_j[pos] = j; s_v[pos] = v; }
        pos++;
    }
    __syncthreads();
    int cnt = min(total, CAP);

    if (cnt == 0) {
        // all-masked row: softmax one-hot at argmax(-9e15*(1+g*S)) = argmin S
        float bm = 3.4e38f; int bj = 0;
        for (int j = tid; j < NN; j += 256) {
            float s = S[(size_t)i * NN + j];
            if (s < bm) { bm = s; bj = j; }
        }
        s_fm[tid] = bm; s_fi[tid] = bj;
        __syncthreads();
        for (int s = 128; s > 0; s >>= 1) {
            if (tid < s) {
                if (s_fm[tid + s] < s_fm[tid] ||
                    (s_fm[tid + s] == s_fm[tid] && s_fi[tid + s] < s_fi[tid])) {
                    s_fm[tid] = s_fm[tid + s]; s_fi[tid] = s_fi[tid + s];
                }
            }
            __syncthreads();
        }
        if (tid < OUT_F) {
            float r = g_Wh[(size_t)s_fi[0] * OUT_F + tid];
            out[(size_t)i * OUT_F + tid] = (r > 0.f) ? r : expm1f(r);
        }
        return;
    }

    // --- row max (stable softmax) ---
    float m = -3.4e38f;
    for (int k = tid; k < cnt; k += 256) m = fmaxf(m, s_v[k]);
    #pragma unroll
    for (int o = 16; o > 0; o >>= 1) m = fmaxf(m, __shfl_xor_sync(0xffffffffu, m, o));
    if (lane == 0) s_red[wid] = m;
    __syncthreads();
    if (tid == 0) {
        float mm = s_red[0];
        #pragma unroll
        for (int q = 1; q < 8; q++) mm = fmaxf(mm, s_red[q]);
        s_bcast = mm;
    }
    __syncthreads();
    m = s_bcast;
    __syncthreads();           // s_bcast is rewritten below

    // --- exponentiate in place + row sum ---
    float ls = 0.f;
    for (int k = tid; k < cnt; k += 256) {
        float p = __expf(s_v[k] - m);
        s_v[k] = p;
        ls += p;
    }
    #pragma unroll
    for (int o = 16; o > 0; o >>= 1) ls += __shfl_xor_sync(0xffffffffu, ls, o);
    if (lane == 0) s_red[wid] = ls;
    __syncthreads();
    if (tid == 0) {
        float tt = 0.f;
        #pragma unroll
        for (int q = 0; q < 8; q++) tt += s_red[q];
        s_bcast = tt;
    }
    __syncthreads();
    const float inv_l = 1.0f / s_bcast;

    // --- weighted aggregation of Wh rows (2-way parallel over k) + elu ---
    {
        const int col  = tid & 127;
        const int half = tid >> 7;
        float acc = 0.f;
        for (int k = half; k < cnt; k += 2)
            acc = fmaf(s_v[k], g_Wh[(size_t)s_j[k] * OUT_F + col], acc);
        s_fm[tid] = acc;                  // reuse as partial buffer
        __syncthreads();
        if (tid < OUT_F) {
            float r = (s_fm[tid] + s_fm[tid + 128]) * inv_l;
            out[(size_t)i * OUT_F + tid] = (r > 0.f) ? r : expm1f(r);
        }
    }
}

// ---------------- launch ----------------
extern "C" void kernel_launch(void* const* d_in, const int* in_sizes, int n_in,
                              void* d_out, int out_size) {
    const float* p_h = nullptr;
    const void*  p_e = nullptr;
    const float* p_S = nullptr;
    const float* p_W = nullptr;
    const float* p_a = nullptr;
    const float* p_g = nullptr;

    for (int k = 0; k < n_in; k++) {
        switch (in_sizes[k]) {
            case NN * IN_F:    p_h = (const float*)d_in[k]; break; // 2097152
            case 2 * NE:       p_e = d_in[k];               break; // 524288
            case NN * NN:      p_S = (const float*)d_in[k]; break; // 67108864
            case IN_F * OUT_F: p_W = (const float*)d_in[k]; break; // 32768
            case 2 * OUT_F:    p_a = (const float*)d_in[k]; break; // 256
            case 1:            p_g = (const float*)d_in[k]; break;
        }
    }
    float* out = (float*)d_out;

    detect_kernel<<<1, 32>>>((const long long*)p_e);
    clear_adj_kernel<<<(NN * WORDS_PER_ROW / 4 + 255) / 256, 256>>>();
    scatter_kernel<<<(NE + 255) / 256, 256>>>(p_e);
    gemm_kernel<<<512, 128>>>(p_h, p_W);
    epi_kernel<<<NN / 32, 256>>>(p_a);
    attn_kernel<<<NN, 256>>>(p_S, p_g, out);
}

// round 10
// speedup vs baseline: 1.8967x; 1.2330x over previous
#include <cuda_runtime.h>
#include <cuda_bf16.h>
#include <cstdint>

// Problem constants
#define NN     8192
#define IN_F   256
#define OUT_F  128
#define NE     262144
#define WORDS_PER_ROW (NN / 32)   // 256
#define CAPW   128                // per-warp neighbor capacity; Poisson(32) tail ~0

// ---------------- scratch (static device globals; no runtime alloc) ----------------
__device__ float        g_P0 [NN * OUT_F];         // 4 MB split-K partial 0
__device__ float        g_P1 [NN * OUT_F];         // 4 MB split-K partial 1
__device__ float        g_Wh [NN * OUT_F];         // 4 MB
__device__ float        g_Wh1[NN];
__device__ float        g_Wh2[NN];
__device__ unsigned int g_adj[NN * WORDS_PER_ROW]; // 8 MB bitmask
__device__ int          g_mode;                    // 1 = int64 edge_index, 0 = int32

// ---------------- kernel: detect edge_index dtype ----------------
__global__ void detect_kernel(const long long* __restrict__ ei) {
    int t = threadIdx.x;                               // 32 threads
    long long v = ei[(size_t)t * (2 * NE / 32 / 2)];   // spread over first half
    int bad = (v < 0 || v >= NN) ? 1 : 0;
    unsigned m = __ballot_sync(0xffffffffu, bad);
    if (t == 0) g_mode = (m == 0u) ? 1 : 0;
}

// ---------------- kernel: clear adjacency bitmask (vectorized) ----------------
__global__ void clear_adj_kernel() {
    size_t idx = (size_t)blockIdx.x * blockDim.x + threadIdx.x;
    size_t n4  = (size_t)NN * WORDS_PER_ROW / 4;
    if (idx < n4) reinterpret_cast<uint4*>(g_adj)[idx] = make_uint4(0u, 0u, 0u, 0u);
}

// ---------------- kernel: scatter edges into bitmask (dedup via OR) ----------------
__global__ void scatter_kernel(const void* __restrict__ eptr) {
    int e = blockIdx.x * blockDim.x + threadIdx.x;
    if (e >= NE) return;
    int i, j;
    if (g_mode) {
        const long long* p = (const long long*)eptr;
        i = (int)p[e];
        j = (int)p[NE + e];
    } else {
        const int* p = (const int*)eptr;
        i = p[e];
        j = p[NE + e];
    }
    i &= (NN - 1);
    j &= (NN - 1);
    atomicOr(&g_adj[i * WORDS_PER_ROW + (j >> 5)], 1u << (j & 31));
}

// ---------------- kernel: split-K GEMM, 8 rows x 4 cols per thread ----------------
// grid = 512: blockIdx>>1 = row tile (32 rows), blockIdx&1 = K half (128).
// 128 threads: tx = tid&31 -> cols tx*4..+3 ; ty = tid>>5 (0..3) -> rows ty*8..+7.
__global__ void gemm_kernel(const float* __restrict__ h, const float* __restrict__ W) {
    __shared__ float hs[32][32];
    __shared__ float Ws[32][128];
    const int row0 = (blockIdx.x >> 1) * 32;
    const int ks   = (blockIdx.x & 1) * 128;
    const int tid  = threadIdx.x;
    const int tx   = tid & 31;
    const int ty   = tid >> 5;

    float acc[8][4];
    #pragma unroll
    for (int r = 0; r < 8; r++)
        #pragma unroll
        for (int c = 0; c < 4; c++) acc[r][c] = 0.f;

    #pragma unroll
    for (int kt = 0; kt < 128; kt += 32) {
        const int k0 = ks + kt;
        #pragma unroll
        for (int q = 0; q < 2; q++) {
            int idx = tid + q * 128;
            int r   = idx >> 3;
            int c4  = (idx & 7) * 4;
            *reinterpret_cast<float4*>(&hs[r][c4]) =
                *reinterpret_cast<const float4*>(&h[(size_t)(row0 + r) * IN_F + k0 + c4]);
        }
        #pragma unroll
        for (int q = 0; q < 8; q++) {
            int kk = ty + q * 4;
            *reinterpret_cast<float4*>(&Ws[kk][tx * 4]) =
                *reinterpret_cast<const float4*>(&W[(size_t)(k0 + kk) * OUT_F + tx * 4]);
        }
        __syncthreads();
        #pragma unroll
        for (int kk = 0; kk < 32; kk += 4) {
            float4 b0 = *reinterpret_cast<const float4*>(&Ws[kk + 0][tx * 4]);
            float4 b1 = *reinterpret_cast<const float4*>(&Ws[kk + 1][tx * 4]);
            float4 b2 = *reinterpret_cast<const float4*>(&Ws[kk + 2][tx * 4]);
            float4 b3 = *reinterpret_cast<const float4*>(&Ws[kk + 3][tx * 4]);
            #pragma unroll
            for (int r = 0; r < 8; r++) {
                float4 av = *reinterpret_cast<const float4*>(&hs[ty * 8 + r][kk]); // broadcast
                acc[r][0] = fmaf(av.x, b0.x, acc[r][0]);
                acc[r][1] = fmaf(av.x, b0.y, acc[r][1]);
                acc[r][2] = fmaf(av.x, b0.z, acc[r][2]);
                acc[r][3] = fmaf(av.x, b0.w, acc[r][3]);
                acc[r][0] = fmaf(av.y, b1.x, acc[r][0]);
                acc[r][1] = fmaf(av.y, b1.y, acc[r][1]);
                acc[r][2] = fmaf(av.y, b1.z, acc[r][2]);
                acc[r][3] = fmaf(av.y, b1.w, acc[r][3]);
                acc[r][0] = fmaf(av.z, b2.x, acc[r][0]);
                acc[r][1] = fmaf(av.z, b2.y, acc[r][1]);
                acc[r][2] = fmaf(av.z, b2.z, acc[r][2]);
                acc[r][3] = fmaf(av.z, b2.w, acc[r][3]);
                acc[r][0] = fmaf(av.w, b3.x, acc[r][0]);
                acc[r][1] = fmaf(av.w, b3.y, acc[r][1]);
                acc[r][2] = fmaf(av.w, b3.z, acc[r][2]);
                acc[r][3] = fmaf(av.w, b3.w, acc[r][3]);
            }
        }
        __syncthreads();
    }
    float* dst = (blockIdx.x & 1) ? g_P1 : g_P0;
    #pragma unroll
    for (int r = 0; r < 8; r++)
        *reinterpret_cast<float4*>(&dst[(size_t)(row0 + ty * 8 + r) * OUT_F + tx * 4]) =
            make_float4(acc[r][0], acc[r][1], acc[r][2], acc[r][3]);
}

// ---------------- kernel: epilogue — Wh = P0+P1, Wh1/Wh2 dots fused ----------------
__global__ void epi_kernel(const float* __restrict__ a) {
    const int row0 = blockIdx.x * 32;
    const int tid  = threadIdx.x;
    const int tx   = tid & 31;
    const int ty   = tid >> 5;

    const float4 a1 = *reinterpret_cast<const float4*>(&a[tx * 4]);
    const float4 a2 = *reinterpret_cast<const float4*>(&a[OUT_F + tx * 4]);

    float p1[4], p2[4];
    #pragma unroll
    for (int r = 0; r < 4; r++) {
        size_t off = (size_t)(row0 + ty * 4 + r) * OUT_F + tx * 4;
        float4 v0 = *reinterpret_cast<const float4*>(&g_P0[off]);
        float4 v1 = *reinterpret_cast<const float4*>(&g_P1[off]);
        float4 w  = make_float4(v0.x + v1.x, v0.y + v1.y, v0.z + v1.z, v0.w + v1.w);
        *reinterpret_cast<float4*>(&g_Wh[off]) = w;
        p1[r] = fmaf(w.x, a1.x, fmaf(w.y, a1.y, fmaf(w.z, a1.z, w.w * a1.w)));
        p2[r] = fmaf(w.x, a2.x, fmaf(w.y, a2.y, fmaf(w.z, a2.z, w.w * a2.w)));
    }
    #pragma unroll
    for (int o = 16; o > 0; o >>= 1) {
        #pragma unroll
        for (int r = 0; r < 4; r++) {
            p1[r] += __shfl_xor_sync(0xffffffffu, p1[r], o);
            p2[r] += __shfl_xor_sync(0xffffffffu, p2[r], o);
        }
    }
    if (tx == 0) {
        #pragma unroll
        for (int r = 0; r < 4; r++) {
            g_Wh1[row0 + ty * 4 + r] = p1[r];
            g_Wh2[row0 + ty * 4 + r] = p2[r];
        }
    }
}

// ---------------- kernel: warp-per-row sparse attention + aggregation + elu --------
// 8 warps/block, one row per warp. No block barriers; all warp-synchronous.
__global__ void attn_kernel(const float* __restrict__ S,
                            const float* __restrict__ raw_gamma,
                            float* __restrict__ out) {
    const int tid  = threadIdx.x;
    const int lane = tid & 31;
    const int wid  = tid >> 5;                 // 0..7
    const int i    = blockIdx.x * 8 + wid;     // row

    __shared__ int   s_j[8][CAPW];
    __shared__ float s_v[8][CAPW];

    const float gamma = log1pf(expf(raw_gamma[0]));  // softplus
    const float wh1   = g_Wh1[i];

    // --- read 256 bitmask words: 8 lane-strided (coalesced) per lane ---
    unsigned wq[8];
    int mycnt = 0;
    #pragma unroll
    for (int q = 0; q < 8; q++) {
        wq[q] = g_adj[i * WORDS_PER_ROW + q * 32 + lane];
        mycnt += __popc(wq[q]);
    }
    // warp exclusive scan -> deterministic append base per lane
    int incl = mycnt;
    #pragma unroll
    for (int o = 1; o < 32; o <<= 1) {
        int n = __shfl_up_sync(0xffffffffu, incl, o);
        if (lane >= o) incl += n;
    }
    int pos   = incl - mycnt;
    int total = __shfl_sync(0xffffffffu, incl, 31);
    int cnt   = min(total, CAPW);

    // --- expand bits -> (j, v) list; fixed order => deterministic fp results ---
    #pragma unroll
    for (int q = 0; q < 8; q++) {
        unsigned w = wq[q];
        while (w) {
            int b = __ffs(w) - 1;
            w &= w - 1;
            int j = ((q * 32 + lane) << 5) + b;
            float x = wh1 + g_Wh2[j];
            float e = (x > 0.f) ? x : 0.2f * x;                       // leaky_relu
            float v = e * fmaf(gamma, S[(size_t)i * NN + j], 1.0f);   // *(1+gamma*S)
            if (pos < CAPW) { s_j[wid][pos] = j; s_v[wid][pos] = v; }
            pos++;
        }
    }
    __syncwarp();

    if (cnt == 0) {
        // all-masked row: softmax one-hot at argmax(-9e15*(1+g*S)) = argmin S
        float bm = 3.4e38f; int bj = 0;
        for (int j = lane; j < NN; j += 32) {
            float s = S[(size_t)i * NN + j];
            if (s < bm || (s == bm && j < bj)) { bm = s; bj = j; }
        }
        #pragma unroll
        for (int o = 16; o > 0; o >>= 1) {
            float os = __shfl_xor_sync(0xffffffffu, bm, o);
            int   oj = __shfl_xor_sync(0xffffffffu, bj, o);
            if (os < bm || (os == bm && oj < bj)) { bm = os; bj = oj; }
        }
        float4 r = *reinterpret_cast<const float4*>(&g_Wh[(size_t)bj * OUT_F + lane * 4]);
        float4 o4;
        o4.x = (r.x > 0.f) ? r.x : expm1f(r.x);
        o4.y = (r.y > 0.f) ? r.y : expm1f(r.y);
        o4.z = (r.z > 0.f) ? r.z : expm1f(r.z);
        o4.w = (r.w > 0.f) ? r.w : expm1f(r.w);
        *reinterpret_cast<float4*>(&out[(size_t)i * OUT_F + lane * 4]) = o4;
        return;
    }

    // --- row max ---
    float m = -3.4e38f;
    for (int k = lane; k < cnt; k += 32) m = fmaxf(m, s_v[wid][k]);
    #pragma unroll
    for (int o = 16; o > 0; o >>= 1) m = fmaxf(m, __shfl_xor_sync(0xffffffffu, m, o));

    // --- exp in place + sum ---
    float ls = 0.f;
    for (int k = lane; k < cnt; k += 32) {
        float p = __expf(s_v[wid][k] - m);
        s_v[wid][k] = p;
        ls += p;
    }
    #pragma unroll
    for (int o = 16; o > 0; o >>= 1) ls += __shfl_xor_sync(0xffffffffu, ls, o);
    const float inv_l = 1.0f / ls;
    __syncwarp();

    // --- aggregation: lane owns cols lane*4..+3; serial over neighbors (MLP via x2) ---
    float4 acc = make_float4(0.f, 0.f, 0.f, 0.f);
    int k = 0;
    for (; k + 2 <= cnt; k += 2) {
        float p0 = s_v[wid][k],     p1 = s_v[wid][k + 1];
        int   j0 = s_j[wid][k],     j1 = s_j[wid][k + 1];
        float4 w0 = *reinterpret_cast<const float4*>(&g_Wh[(size_t)j0 * OUT_F + lane * 4]);
        float4 w1 = *reinterpret_cast<const float4*>(&g_Wh[(size_t)j1 * OUT_F + lane * 4]);
        acc.x = fmaf(p0, w0.x, acc.x); acc.y = fmaf(p0, w0.y, acc.y);
        acc.z = fmaf(p0, w0.z, acc.z); acc.w = fmaf(p0, w0.w, acc.w);
        acc.x = fmaf(p1, w1.x, acc.x); acc.y = fmaf(p1, w1.y, acc.y);
        acc.z = fmaf(p1, w1.z, acc.z); acc.w = fmaf(p1, w1.w, acc.w);
    }
    if (k < cnt) {
        float p0 = s_v[wid][k];
        float4 w0 = *reinterpret_cast<const float4*>(&g_Wh[(size_t)s_j[wid][k] * OUT_F + lane * 4]);
        acc.x = fmaf(p0, w0.x, acc.x); acc.y = fmaf(p0, w0.y, acc.y);
        acc.z = fmaf(p0, w0.z, acc.z); acc.w = fmaf(p0, w0.w, acc.w);
    }
    float4 o4;
    float rx = acc.x * inv_l, ry = acc.y * inv_l, rz = acc.z * inv_l, rw = acc.w * inv_l;
    o4.x = (rx > 0.f) ? rx : expm1f(rx);
    o4.y = (ry > 0.f) ? ry : expm1f(ry);
    o4.z = (rz > 0.f) ? rz : expm1f(rz);
    o4.w = (rw > 0.f) ? rw : expm1f(rw);
    *reinterpret_cast<float4*>(&out[(size_t)i * OUT_F + lane * 4]) = o4;
}

// ---------------- launch ----------------
extern "C" void kernel_launch(void* const* d_in, const int* in_sizes, int n_in,
                              void* d_out, int out_size) {
    const float* p_h = nullptr;
    const void*  p_e = nullptr;
    const float* p_S = nullptr;
    const float* p_W = nullptr;
    const float* p_a = nullptr;
    const float* p_g = nullptr;

    for (int k = 0; k < n_in; k++) {
        switch (in_sizes[k]) {
            case NN * IN_F:    p_h = (const float*)d_in[k]; break; // 2097152
            case 2 * NE:       p_e = d_in[k];               break; // 524288
            case NN * NN:      p_S = (const float*)d_in[k]; break; // 67108864
            case IN_F * OUT_F: p_W = (const float*)d_in[k]; break; // 32768
            case 2 * OUT_F:    p_a = (const float*)d_in[k]; break; // 256
            case 1:            p_g = (const float*)d_in[k]; break;
        }
    }
    float* out = (float*)d_out;

    detect_kernel<<<1, 32>>>((const long long*)p_e);
    clear_adj_kernel<<<(NN * WORDS_PER_ROW / 4 + 255) / 256, 256>>>();
    scatter_kernel<<<(NE + 255) / 256, 256>>>(p_e);
    gemm_kernel<<<512, 128>>>(p_h, p_W);
    epi_kernel<<<NN / 32, 256>>>(p_a);
    attn_kernel<<<NN / 8, 256>>>(p_S, p_g, out);
}